// round 14
// baseline (speedup 1.0000x reference)
#include <cuda_runtime.h>
#include <cuda_fp16.h>
#include <math.h>
#include <stdint.h>

#define NB   8192
#define NIN  1024
#define NHID 4096
#define NOUT 1024
#define NE   8
#define EPS  1e-5f

__device__ __align__(256) __half g_Xh [(size_t)NB * NIN];
__device__ __align__(256) __half g_Wh1[(size_t)NE * NHID * NIN];   // [E][N][K]
__device__ __align__(256) __half g_Wh2[(size_t)NE * NOUT * NHID];  // [E][N][K]
__device__ __align__(256) __half g_Hh [(size_t)NE * NB * NHID];    // pre-LN then act
__device__ __align__(256) __half g_Yh [(size_t)NE * NB * NOUT];

__device__ __forceinline__ float gelu_exact(float v) {
    return 0.5f * v * (1.0f + erff(v * 0.70710678118654752f));
}
__device__ __forceinline__ void block_sum2(float& s, float& s2) {
    __shared__ float sh[2][8];
    #pragma unroll
    for (int o = 16; o > 0; o >>= 1) {
        s  += __shfl_xor_sync(0xffffffffu, s,  o);
        s2 += __shfl_xor_sync(0xffffffffu, s2, o);
    }
    const int w = threadIdx.x >> 5, lane = threadIdx.x & 31;
    if (lane == 0) { sh[0][w] = s; sh[1][w] = s2; }
    __syncthreads();
    float t = 0.f, t2 = 0.f;
    const int nw = blockDim.x >> 5;
    for (int i = 0; i < nw; i++) { t += sh[0][i]; t2 += sh[1][i]; }
    s = t; s2 = t2;
    __syncthreads();
}
__device__ __forceinline__ uint32_t packh2(float a, float b) {
    __half2 h = __floats2half2_rn(a, b);
    return *reinterpret_cast<uint32_t*>(&h);
}

// ---------------- prep kernels ----------------
__global__ __launch_bounds__(256)
void cast_x_kernel(const float* __restrict__ X, __half* __restrict__ P)
{
    const size_t row = blockIdx.x;
    const int tid = threadIdx.x;
    const float4 v = ((const float4*)(X + row * NIN))[tid];
    *(uint2*)(P + row * NIN + tid * 4) = make_uint2(packh2(v.x, v.y), packh2(v.z, v.w));
}

__global__ __launch_bounds__(256)
void transpose_cast_kernel(const float* __restrict__ W, __half* __restrict__ Wh,
                           int K, int N)
{
    __shared__ float s[32][257];
    const int tid = threadIdx.x;
    const int e = blockIdx.z, n0 = blockIdx.x * 256, k0 = blockIdx.y * 32;
    const float* We = W + (size_t)e * K * N;
    for (int r = 0; r < 32; r++)
        s[r][tid] = We[(size_t)(k0 + r) * N + n0 + tid];
    __syncthreads();
    uint32_t buf[16];
    #pragma unroll
    for (int r = 0; r < 32; r += 2)
        buf[r >> 1] = packh2(s[r][tid], s[r + 1][tid]);
    __half* dst = Wh + ((size_t)e * N + n0 + tid) * (size_t)K + k0;
    #pragma unroll
    for (int j = 0; j < 4; j++)
        *(uint4*)(dst + j * 8) = ((const uint4*)buf)[j];
}

// ---------------- fp16 mma.sync GEMM (single expert, pre-offset ptrs) -------
// C[M,N] = A @ B^T + bias.  A,B fp16 K-major rows.
// CTA 128x128, 4 warps (2M x 2N), warp 64x64, BK=64, 3-stage cp.async,
// 2 CTAs/SM, fragment double-buffering, one barrier per k-block.
#define STG_A   16384
#define STG_B   16384
#define STG     (STG_A + STG_B)
#define GSMEM   (3 * STG)

template<bool OUT_F16>
__global__ void __launch_bounds__(128, 2)
gemm_f16(const __half* __restrict__ Ap, const __half* __restrict__ Bp,
         const float* __restrict__ bias, void* __restrict__ Cv,
         int M, int N, int K)
{
    extern __shared__ char smem[];
    const uint32_t sb = (uint32_t)__cvta_generic_to_shared(smem);
    const int tid = threadIdx.x;
    const int lane = tid & 31, wid = tid >> 5;
    const int wm = wid & 1, wn = wid >> 1;
    const int row0 = blockIdx.y * 128, col0 = blockIdx.x * 128;
    const size_t rowbytes = (size_t)K * 2;
    const char* Ab = (const char*)Ap + (size_t)row0 * rowbytes;
    const char* Bb = (const char*)Bp + (size_t)col0 * rowbytes;
    const int S = K >> 6;

    auto load_stage = [&](int s) {
        const int buf = s % 3;
        const uint32_t a0 = sb + (uint32_t)buf * STG, b0 = a0 + STG_A;
        #pragma unroll
        for (int k = 0; k < 8; k++) {
            const int c = tid + k * 128;
            const int row = c >> 3, cb = (c & 7) * 16;
            uint32_t off = (uint32_t)(row * 128 + cb);
            off ^= (off >> 3) & 0x70;
            asm volatile("cp.async.cg.shared.global [%0], [%1], 16;"
                         :: "r"(a0 + off),
                            "l"(Ab + (size_t)row * rowbytes + (size_t)s * 128 + cb));
        }
        #pragma unroll
        for (int k = 0; k < 8; k++) {
            const int c = tid + k * 128;
            const int row = c >> 3, cb = (c & 7) * 16;
            uint32_t off = (uint32_t)(row * 128 + cb);
            off ^= (off >> 3) & 0x70;
            asm volatile("cp.async.cg.shared.global [%0], [%1], 16;"
                         :: "r"(b0 + off),
                            "l"(Bb + (size_t)row * rowbytes + (size_t)s * 128 + cb));
        }
        asm volatile("cp.async.commit_group;" ::: "memory");
    };

    float acc[4][8][4] = {};

    load_stage(0);
    load_stage(1);

    const int arow = wm * 64 + (lane & 15);
    const int acolsel = (lane >> 4) << 4;
    const int brow_l = ((lane >> 4) << 3) + (lane & 7);
    const int bcolsel = ((lane >> 3) & 1) << 4;

    uint32_t afr[2][4][4], bfr[2][4][4];

    auto load_frags = [&](int slot, uint32_t asA, uint32_t asB, int h) {
        const int acol = h * 32 + acolsel;
        #pragma unroll
        for (int i = 0; i < 4; i++) {
            uint32_t byt = (uint32_t)((arow + i * 16) * 128 + acol);
            byt ^= (byt >> 3) & 0x70;
            asm volatile(
                "ldmatrix.sync.aligned.m8n8.x4.shared.b16 {%0,%1,%2,%3}, [%4];"
                : "=r"(afr[slot][i][0]), "=r"(afr[slot][i][1]),
                  "=r"(afr[slot][i][2]), "=r"(afr[slot][i][3])
                : "r"(asA + byt));
        }
        const int bcol = h * 32 + bcolsel;
        #pragma unroll
        for (int j2 = 0; j2 < 4; j2++) {
            const int brow = wn * 64 + j2 * 16 + brow_l;
            uint32_t byt = (uint32_t)(brow * 128 + bcol);
            byt ^= (byt >> 3) & 0x70;
            asm volatile(
                "ldmatrix.sync.aligned.m8n8.x4.shared.b16 {%0,%1,%2,%3}, [%4];"
                : "=r"(bfr[slot][j2][0]), "=r"(bfr[slot][j2][1]),
                  "=r"(bfr[slot][j2][2]), "=r"(bfr[slot][j2][3])
                : "r"(asB + byt));
        }
    };

    for (int kb = 0; kb < S; kb++) {
        asm volatile("cp.async.wait_group 1;" ::: "memory");
        __syncthreads();
        if (kb + 2 < S) load_stage(kb + 2);
        else asm volatile("cp.async.commit_group;" ::: "memory");

        const int buf = kb % 3;
        const uint32_t asA = sb + (uint32_t)buf * STG;
        const uint32_t asB = asA + STG_A;

        load_frags(0, asA, asB, 0);
        #pragma unroll
        for (int h = 0; h < 4; h++) {
            const int cur = h & 1, nxt = cur ^ 1;
            if (h < 3) load_frags(nxt, asA, asB, h + 1);
            #pragma unroll
            for (int i = 0; i < 4; i++)
                #pragma unroll
                for (int j2 = 0; j2 < 4; j2++)
                    #pragma unroll
                    for (int t = 0; t < 2; t++) {
                        float* d = acc[i][j2 * 2 + t];
                        asm volatile(
                            "mma.sync.aligned.m16n8k16.row.col.f32.f16.f16.f32 "
                            "{%0,%1,%2,%3},{%4,%5,%6,%7},{%8,%9},{%0,%1,%2,%3};"
                            : "+f"(d[0]), "+f"(d[1]), "+f"(d[2]), "+f"(d[3])
                            : "r"(afr[cur][i][0]), "r"(afr[cur][i][1]),
                              "r"(afr[cur][i][2]), "r"(afr[cur][i][3]),
                              "r"(bfr[cur][j2][2 * t]), "r"(bfr[cur][j2][2 * t + 1]));
                    }
        }
    }

    // Epilogue: warp owns 64x64 at (row0 + wm*64, col0 + wn*64)
    const float* bz = bias + col0 + wn * 64;
    const int r = lane >> 2, cc = (lane & 3) * 2;
    if (OUT_F16) {
        __half* Cb = (__half*)Cv + (size_t)(row0 + wm * 64) * N + col0 + wn * 64;
        #pragma unroll
        for (int i = 0; i < 4; i++)
            #pragma unroll
            for (int j = 0; j < 8; j++) {
                const int col = j * 8 + cc;
                const float b0v = bz[col], b1v = bz[col + 1];
                *(uint32_t*)(Cb + (size_t)(i * 16 + r) * N + col) =
                    packh2(acc[i][j][0] + b0v, acc[i][j][1] + b1v);
                *(uint32_t*)(Cb + (size_t)(i * 16 + r + 8) * N + col) =
                    packh2(acc[i][j][2] + b0v, acc[i][j][3] + b1v);
            }
    } else {
        float* Cb = (float*)Cv + (size_t)(row0 + wm * 64) * N + col0 + wn * 64;
        #pragma unroll
        for (int i = 0; i < 4; i++)
            #pragma unroll
            for (int j = 0; j < 8; j++) {
                const int col = j * 8 + cc;
                const float b0v = bz[col], b1v = bz[col + 1];
                *(float2*)(Cb + (size_t)(i * 16 + r) * N + col) =
                    make_float2(acc[i][j][0] + b0v, acc[i][j][1] + b1v);
                *(float2*)(Cb + (size_t)(i * 16 + r + 8) * N + col) =
                    make_float2(acc[i][j][2] + b0v, acc[i][j][3] + b1v);
            }
    }
}

// ---------------- in-place LN + GELU on fp16 rows (single expert) ----------
__global__ __launch_bounds__(256)
void ln_gelu_f16(__half* __restrict__ Hh,
                 const float* __restrict__ gamma, const float* __restrict__ beta)
{
    const size_t row = blockIdx.x;
    const int tid = threadIdx.x;
    uint4* xr = (uint4*)(Hh + row * (size_t)NHID);
    const float4* gp = (const float4*)gamma;
    const float4* bp = (const float4*)beta;

    uint4 u[2];
    float v[16];
    float s = 0.f, s2 = 0.f;
    #pragma unroll
    for (int i = 0; i < 2; i++) {
        u[i] = xr[i * 256 + tid];
        const uint32_t* w32 = (const uint32_t*)&u[i];
        #pragma unroll
        for (int q = 0; q < 4; q++) {
            float2 f = __half22float2(*(const __half2*)&w32[q]);
            v[i * 8 + q * 2]     = f.x;
            v[i * 8 + q * 2 + 1] = f.y;
            s  += f.x + f.y;
            s2 += f.x * f.x + f.y * f.y;
        }
    }
    block_sum2(s, s2);
    const float mean = s * (1.0f / NHID);
    const float rstd = rsqrtf(s2 * (1.0f / NHID) - mean * mean + EPS);

    #pragma unroll
    for (int i = 0; i < 2; i++) {
        uint4 o;
        uint32_t* ow = (uint32_t*)&o;
        #pragma unroll
        for (int q = 0; q < 2; q++) {
            const int eb = (i * 256 + tid) * 8 + q * 4;
            const float4 g4 = gp[eb >> 2], b4 = bp[eb >> 2];
            const float* vv = &v[i * 8 + q * 4];
            float a0 = gelu_exact((vv[0] - mean) * rstd * g4.x + b4.x);
            float a1 = gelu_exact((vv[1] - mean) * rstd * g4.y + b4.y);
            float a2 = gelu_exact((vv[2] - mean) * rstd * g4.z + b4.z);
            float a3 = gelu_exact((vv[3] - mean) * rstd * g4.w + b4.w);
            ow[q * 2]     = packh2(a0, a1);
            ow[q * 2 + 1] = packh2(a2, a3);
        }
        xr[i * 256 + tid] = o;
    }
}

// ---------------- final LN+GELU+weighted combine (fp16 Y) ----------------
__global__ __launch_bounds__(256)
void combine_kernel(const float* __restrict__ w,
                    const float* __restrict__ g2, const float* __restrict__ be2,
                    float* __restrict__ out)
{
    const int b = blockIdx.x, tid = threadIdx.x;
    float acc[4] = {0.f, 0.f, 0.f, 0.f};
    for (int e = 0; e < NE; e++) {
        const __half* yr = g_Yh + ((size_t)e * NB + b) * NOUT;
        const uint2 u = *(const uint2*)(yr + tid * 4);
        float2 f0 = __half22float2(*(const __half2*)&u.x);
        float2 f1 = __half22float2(*(const __half2*)&u.y);
        float vv[4] = {f0.x, f0.y, f1.x, f1.y};
        float s = vv[0] + vv[1] + vv[2] + vv[3];
        float s2 = vv[0]*vv[0] + vv[1]*vv[1] + vv[2]*vv[2] + vv[3]*vv[3];
        block_sum2(s, s2);
        const float mean = s * (1.0f / NOUT);
        const float rstd = rsqrtf(s2 * (1.0f / NOUT) - mean * mean + EPS);
        const float we = w[(size_t)b * NE + e];
        const float4 g4 = *(const float4*)(g2 + (size_t)e * NOUT + tid * 4);
        const float4 b4 = *(const float4*)(be2 + (size_t)e * NOUT + tid * 4);
        acc[0] += we * gelu_exact((vv[0] - mean) * rstd * g4.x + b4.x);
        acc[1] += we * gelu_exact((vv[1] - mean) * rstd * g4.y + b4.y);
        acc[2] += we * gelu_exact((vv[2] - mean) * rstd * g4.z + b4.z);
        acc[3] += we * gelu_exact((vv[3] - mean) * rstd * g4.w + b4.w);
    }
    *(float4*)(out + (size_t)b * NOUT + tid * 4) =
        make_float4(acc[0], acc[1], acc[2], acc[3]);
}

// ---------------------------------------------------------------------------
extern "C" void kernel_launch(void* const* d_in, const int* in_sizes, int n_in,
                              void* d_out, int out_size)
{
    const float* x   = (const float*)d_in[0];
    const float* wts = (const float*)d_in[1];
    const float* W1  = (const float*)d_in[2];
    const float* b1  = (const float*)d_in[3];
    const float* g1  = (const float*)d_in[4];
    const float* be1 = (const float*)d_in[5];
    const float* W2  = (const float*)d_in[6];
    const float* b2  = (const float*)d_in[7];
    const float* g2  = (const float*)d_in[8];
    const float* be2 = (const float*)d_in[9];
    float* out = (float*)d_out;

    static __half *Xh = nullptr, *Wh1, *Wh2, *Hh, *Yh;
    static cudaStream_t s1;
    static cudaEvent_t evStart, evG1[NE], evDone;
    if (!Xh) {
        cudaGetSymbolAddress((void**)&Xh,  g_Xh);
        cudaGetSymbolAddress((void**)&Wh1, g_Wh1);
        cudaGetSymbolAddress((void**)&Wh2, g_Wh2);
        cudaGetSymbolAddress((void**)&Hh,  g_Hh);
        cudaGetSymbolAddress((void**)&Yh,  g_Yh);
        cudaStreamCreateWithFlags(&s1, cudaStreamNonBlocking);
        cudaEventCreateWithFlags(&evStart, cudaEventDisableTiming);
        for (int e = 0; e < NE; e++)
            cudaEventCreateWithFlags(&evG1[e], cudaEventDisableTiming);
        cudaEventCreateWithFlags(&evDone, cudaEventDisableTiming);
        cudaFuncSetAttribute((const void*)gemm_f16<true>,
                             cudaFuncAttributeMaxDynamicSharedMemorySize, GSMEM);
    }

    // Fork second stream off the capture (default) stream.
    cudaEventRecord(evStart, 0);
    cudaStreamWaitEvent(s1, evStart, 0);

    // Stream 0: x cast + W1 transpose, then per-expert GEMM1.
    cast_x_kernel<<<NB, 256>>>(x, Xh);
    transpose_cast_kernel<<<dim3(NHID/256, NIN/32, NE), 256>>>(W1, Wh1, NIN, NHID);

    // Stream 1: W2 transpose overlaps GEMM1 work on stream 0.
    transpose_cast_kernel<<<dim3(NOUT/256, NHID/32, NE), 256, 0, s1>>>(
        W2, Wh2, NHID, NOUT);

    const size_t w1sz = (size_t)NHID * NIN;   // per-expert W1 elems
    const size_t w2sz = (size_t)NOUT * NHID;
    const size_t hsz  = (size_t)NB * NHID;
    const size_t ysz  = (size_t)NB * NOUT;

    for (int e = 0; e < NE; e++) {
        gemm_f16<true><<<dim3(NHID/128, NB/128), 128, GSMEM>>>(
            Xh, Wh1 + (size_t)e * w1sz, b1 + (size_t)e * NHID,
            Hh + (size_t)e * hsz, NB, NHID, NIN);
        cudaEventRecord(evG1[e], 0);

        cudaStreamWaitEvent(s1, evG1[e], 0);
        ln_gelu_f16<<<NB, 256, 0, s1>>>(
            Hh + (size_t)e * hsz, g1 + (size_t)e * NHID, be1 + (size_t)e * NHID);
        gemm_f16<true><<<dim3(NOUT/128, NB/128), 128, GSMEM, s1>>>(
            Hh + (size_t)e * hsz, Wh2 + (size_t)e * w2sz, b2 + (size_t)e * NOUT,
            Yh + (size_t)e * ysz, NB, NOUT, NHID);
    }

    // Rejoin: combine on stream 0 after all expert outputs are ready.
    cudaEventRecord(evDone, s1);
    cudaStreamWaitEvent(0, evDone, 0);
    combine_kernel<<<NB, 256>>>(wts, g2, be2, out);
}

// round 15
// speedup vs baseline: 1.0640x; 1.0640x over previous
#include <cuda_runtime.h>
#include <cuda_fp16.h>
#include <math.h>
#include <stdint.h>

#define NB   8192
#define NIN  1024
#define NHID 4096
#define NOUT 1024
#define NE   8
#define EPS  1e-5f

__device__ __align__(256) __half g_Xh [(size_t)NB * NIN];
__device__ __align__(256) __half g_Wh1[(size_t)NE * NHID * NIN];   // [E][N][K]
__device__ __align__(256) __half g_Wh2[(size_t)NE * NOUT * NHID];  // [E][N][K]
__device__ __align__(256) __half g_Hh [(size_t)NE * NB * NHID];    // pre-LN then act
__device__ __align__(256) __half g_Yh [(size_t)NE * NB * NOUT];
__device__ __align__(256) float2 g_St [(size_t)NE * NB];           // mean, rstd of Y rows

__device__ __forceinline__ float gelu_exact(float v) {
    return 0.5f * v * (1.0f + erff(v * 0.70710678118654752f));
}
__device__ __forceinline__ void block_sum2(float& s, float& s2) {
    __shared__ float sh[2][8];
    #pragma unroll
    for (int o = 16; o > 0; o >>= 1) {
        s  += __shfl_xor_sync(0xffffffffu, s,  o);
        s2 += __shfl_xor_sync(0xffffffffu, s2, o);
    }
    const int w = threadIdx.x >> 5, lane = threadIdx.x & 31;
    if (lane == 0) { sh[0][w] = s; sh[1][w] = s2; }
    __syncthreads();
    float t = 0.f, t2 = 0.f;
    const int nw = blockDim.x >> 5;
    for (int i = 0; i < nw; i++) { t += sh[0][i]; t2 += sh[1][i]; }
    s = t; s2 = t2;
    __syncthreads();
}
__device__ __forceinline__ uint32_t packh2(float a, float b) {
    __half2 h = __floats2half2_rn(a, b);
    return *reinterpret_cast<uint32_t*>(&h);
}

// ---------------- prep kernels ----------------
__global__ __launch_bounds__(256)
void cast_x_kernel(const float* __restrict__ X, __half* __restrict__ P)
{
    const size_t row = blockIdx.x;
    const int tid = threadIdx.x;
    const float4 v = ((const float4*)(X + row * NIN))[tid];
    *(uint2*)(P + row * NIN + tid * 4) = make_uint2(packh2(v.x, v.y), packh2(v.z, v.w));
}

__global__ __launch_bounds__(256)
void transpose_cast_kernel(const float* __restrict__ W, __half* __restrict__ Wh,
                           int K, int N)
{
    __shared__ float s[32][257];
    const int tid = threadIdx.x;
    const int e = blockIdx.z, n0 = blockIdx.x * 256, k0 = blockIdx.y * 32;
    const float* We = W + (size_t)e * K * N;
    for (int r = 0; r < 32; r++)
        s[r][tid] = We[(size_t)(k0 + r) * N + n0 + tid];
    __syncthreads();
    uint32_t buf[16];
    #pragma unroll
    for (int r = 0; r < 32; r += 2)
        buf[r >> 1] = packh2(s[r][tid], s[r + 1][tid]);
    __half* dst = Wh + ((size_t)e * N + n0 + tid) * (size_t)K + k0;
    #pragma unroll
    for (int j = 0; j < 4; j++)
        *(uint4*)(dst + j * 8) = ((const uint4*)buf)[j];
}

// ---------------- fp16 mma.sync GEMM (R11 exact) ----------------
// C[e][M,N] = A([e]) @ B[e]^T + bias[e].  A,B fp16 K-major rows.
// CTA 128x128, 4 warps (2M x 2N), warp 64x64, BK=64, 3-stage cp.async,
// 2 CTAs/SM, fragment double-buffering, one barrier per k-block.
#define STG_A   16384
#define STG_B   16384
#define STG     (STG_A + STG_B)
#define GSMEM   (3 * STG)

template<bool A_EXP, bool OUT_F16>
__global__ void __launch_bounds__(128, 2)
gemm_f16(const __half* __restrict__ Ap, const __half* __restrict__ Bp,
         const float* __restrict__ bias, void* __restrict__ Cv,
         int M, int N, int K)
{
    extern __shared__ char smem[];
    const uint32_t sb = (uint32_t)__cvta_generic_to_shared(smem);
    const int tid = threadIdx.x;
    const int lane = tid & 31, wid = tid >> 5;
    const int wm = wid & 1, wn = wid >> 1;
    const int e = blockIdx.z;
    const int row0 = blockIdx.y * 128, col0 = blockIdx.x * 128;
    const size_t rowbytes = (size_t)K * 2;
    const char* Ab = (const char*)Ap + ((A_EXP ? (size_t)e * M : (size_t)0) + row0) * rowbytes;
    const char* Bb = (const char*)Bp + ((size_t)e * N + col0) * rowbytes;
    const int S = K >> 6;

    auto load_stage = [&](int s) {
        const int buf = s % 3;
        const uint32_t a0 = sb + (uint32_t)buf * STG, b0 = a0 + STG_A;
        #pragma unroll
        for (int k = 0; k < 8; k++) {
            const int c = tid + k * 128;
            const int row = c >> 3, cb = (c & 7) * 16;
            uint32_t off = (uint32_t)(row * 128 + cb);
            off ^= (off >> 3) & 0x70;
            asm volatile("cp.async.cg.shared.global [%0], [%1], 16;"
                         :: "r"(a0 + off),
                            "l"(Ab + (size_t)row * rowbytes + (size_t)s * 128 + cb));
        }
        #pragma unroll
        for (int k = 0; k < 8; k++) {
            const int c = tid + k * 128;
            const int row = c >> 3, cb = (c & 7) * 16;
            uint32_t off = (uint32_t)(row * 128 + cb);
            off ^= (off >> 3) & 0x70;
            asm volatile("cp.async.cg.shared.global [%0], [%1], 16;"
                         :: "r"(b0 + off),
                            "l"(Bb + (size_t)row * rowbytes + (size_t)s * 128 + cb));
        }
        asm volatile("cp.async.commit_group;" ::: "memory");
    };

    float acc[4][8][4] = {};

    load_stage(0);
    load_stage(1);

    const int arow = wm * 64 + (lane & 15);
    const int acolsel = (lane >> 4) << 4;
    const int brow_l = ((lane >> 4) << 3) + (lane & 7);
    const int bcolsel = ((lane >> 3) & 1) << 4;

    uint32_t afr[2][4][4], bfr[2][4][4];

    auto load_frags = [&](int slot, uint32_t asA, uint32_t asB, int h) {
        const int acol = h * 32 + acolsel;
        #pragma unroll
        for (int i = 0; i < 4; i++) {
            uint32_t byt = (uint32_t)((arow + i * 16) * 128 + acol);
            byt ^= (byt >> 3) & 0x70;
            asm volatile(
                "ldmatrix.sync.aligned.m8n8.x4.shared.b16 {%0,%1,%2,%3}, [%4];"
                : "=r"(afr[slot][i][0]), "=r"(afr[slot][i][1]),
                  "=r"(afr[slot][i][2]), "=r"(afr[slot][i][3])
                : "r"(asA + byt));
        }
        const int bcol = h * 32 + bcolsel;
        #pragma unroll
        for (int j2 = 0; j2 < 4; j2++) {
            const int brow = wn * 64 + j2 * 16 + brow_l;
            uint32_t byt = (uint32_t)(brow * 128 + bcol);
            byt ^= (byt >> 3) & 0x70;
            asm volatile(
                "ldmatrix.sync.aligned.m8n8.x4.shared.b16 {%0,%1,%2,%3}, [%4];"
                : "=r"(bfr[slot][j2][0]), "=r"(bfr[slot][j2][1]),
                  "=r"(bfr[slot][j2][2]), "=r"(bfr[slot][j2][3])
                : "r"(asB + byt));
        }
    };

    for (int kb = 0; kb < S; kb++) {
        asm volatile("cp.async.wait_group 1;" ::: "memory");
        __syncthreads();
        if (kb + 2 < S) load_stage(kb + 2);
        else asm volatile("cp.async.commit_group;" ::: "memory");

        const int buf = kb % 3;
        const uint32_t asA = sb + (uint32_t)buf * STG;
        const uint32_t asB = asA + STG_A;

        load_frags(0, asA, asB, 0);
        #pragma unroll
        for (int h = 0; h < 4; h++) {
            const int cur = h & 1, nxt = cur ^ 1;
            if (h < 3) load_frags(nxt, asA, asB, h + 1);
            #pragma unroll
            for (int i = 0; i < 4; i++)
                #pragma unroll
                for (int j2 = 0; j2 < 4; j2++)
                    #pragma unroll
                    for (int t = 0; t < 2; t++) {
                        float* d = acc[i][j2 * 2 + t];
                        asm volatile(
                            "mma.sync.aligned.m16n8k16.row.col.f32.f16.f16.f32 "
                            "{%0,%1,%2,%3},{%4,%5,%6,%7},{%8,%9},{%0,%1,%2,%3};"
                            : "+f"(d[0]), "+f"(d[1]), "+f"(d[2]), "+f"(d[3])
                            : "r"(afr[cur][i][0]), "r"(afr[cur][i][1]),
                              "r"(afr[cur][i][2]), "r"(afr[cur][i][3]),
                              "r"(bfr[cur][j2][2 * t]), "r"(bfr[cur][j2][2 * t + 1]));
                    }
        }
    }

    // Epilogue: warp owns 64x64 at (row0 + wm*64, col0 + wn*64)
    const float* bz = bias + (size_t)e * N + col0 + wn * 64;
    const int r = lane >> 2, cc = (lane & 3) * 2;
    if (OUT_F16) {
        __half* Cb = (__half*)Cv + (size_t)e * M * N
                   + (size_t)(row0 + wm * 64) * N + col0 + wn * 64;
        #pragma unroll
        for (int i = 0; i < 4; i++)
            #pragma unroll
            for (int j = 0; j < 8; j++) {
                const int col = j * 8 + cc;
                const float b0v = bz[col], b1v = bz[col + 1];
                *(uint32_t*)(Cb + (size_t)(i * 16 + r) * N + col) =
                    packh2(acc[i][j][0] + b0v, acc[i][j][1] + b1v);
                *(uint32_t*)(Cb + (size_t)(i * 16 + r + 8) * N + col) =
                    packh2(acc[i][j][2] + b0v, acc[i][j][3] + b1v);
            }
    } else {
        float* Cb = (float*)Cv + (size_t)e * M * N
                  + (size_t)(row0 + wm * 64) * N + col0 + wn * 64;
        #pragma unroll
        for (int i = 0; i < 4; i++)
            #pragma unroll
            for (int j = 0; j < 8; j++) {
                const int col = j * 8 + cc;
                const float b0v = bz[col], b1v = bz[col + 1];
                *(float2*)(Cb + (size_t)(i * 16 + r) * N + col) =
                    make_float2(acc[i][j][0] + b0v, acc[i][j][1] + b1v);
                *(float2*)(Cb + (size_t)(i * 16 + r + 8) * N + col) =
                    make_float2(acc[i][j][2] + b0v, acc[i][j][3] + b1v);
            }
    }
}

// ---------------- in-place LN + GELU on fp16 rows ----------------
__global__ __launch_bounds__(256)
void ln_gelu_f16(__half* __restrict__ Hh,
                 const float* __restrict__ gamma, const float* __restrict__ beta)
{
    const size_t row = blockIdx.x;
    const int e = (int)(row / NB);
    const int tid = threadIdx.x;
    uint4* xr = (uint4*)(Hh + row * (size_t)NHID);
    const float4* gp = (const float4*)(gamma + (size_t)e * NHID);
    const float4* bp = (const float4*)(beta  + (size_t)e * NHID);

    uint4 u[2];
    float v[16];
    float s = 0.f, s2 = 0.f;
    #pragma unroll
    for (int i = 0; i < 2; i++) {
        u[i] = xr[i * 256 + tid];
        const uint32_t* w32 = (const uint32_t*)&u[i];
        #pragma unroll
        for (int q = 0; q < 4; q++) {
            float2 f = __half22float2(*(const __half2*)&w32[q]);
            v[i * 8 + q * 2]     = f.x;
            v[i * 8 + q * 2 + 1] = f.y;
            s  += f.x + f.y;
            s2 += f.x * f.x + f.y * f.y;
        }
    }
    block_sum2(s, s2);
    const float mean = s * (1.0f / NHID);
    const float rstd = rsqrtf(s2 * (1.0f / NHID) - mean * mean + EPS);

    #pragma unroll
    for (int i = 0; i < 2; i++) {
        uint4 o;
        uint32_t* ow = (uint32_t*)&o;
        #pragma unroll
        for (int q = 0; q < 2; q++) {
            const int eb = (i * 256 + tid) * 8 + q * 4;
            const float4 g4 = gp[eb >> 2], b4 = bp[eb >> 2];
            const float* vv = &v[i * 8 + q * 4];
            float a0 = gelu_exact((vv[0] - mean) * rstd * g4.x + b4.x);
            float a1 = gelu_exact((vv[1] - mean) * rstd * g4.y + b4.y);
            float a2 = gelu_exact((vv[2] - mean) * rstd * g4.z + b4.z);
            float a3 = gelu_exact((vv[3] - mean) * rstd * g4.w + b4.w);
            ow[q * 2]     = packh2(a0, a1);
            ow[q * 2 + 1] = packh2(a2, a3);
        }
        xr[i * 256 + tid] = o;
    }
}

// ---------------- Y row stats: warp per row, no barriers ----------------
__global__ __launch_bounds__(256)
void y_stats_kernel(const __half* __restrict__ Yh, float2* __restrict__ St)
{
    const int wid = threadIdx.x >> 5, lane = threadIdx.x & 31;
    const size_t row = (size_t)blockIdx.x * 8 + wid;   // NE*NB rows total
    const uint4* yr = (const uint4*)(Yh + row * NOUT); // 128 uint4 per row
    float s = 0.f, s2 = 0.f;
    #pragma unroll
    for (int i = 0; i < 4; i++) {
        const uint4 u = yr[lane + i * 32];
        const uint32_t* w32 = (const uint32_t*)&u;
        #pragma unroll
        for (int q = 0; q < 4; q++) {
            float2 f = __half22float2(*(const __half2*)&w32[q]);
            s += f.x + f.y;
            s2 += f.x * f.x + f.y * f.y;
        }
    }
    #pragma unroll
    for (int o = 16; o > 0; o >>= 1) {
        s  += __shfl_xor_sync(0xffffffffu, s,  o);
        s2 += __shfl_xor_sync(0xffffffffu, s2, o);
    }
    if (lane == 0) {
        const float mean = s * (1.0f / NOUT);
        const float rstd = rsqrtf(s2 * (1.0f / NOUT) - mean * mean + EPS);
        St[row] = make_float2(mean, rstd);
    }
}

// ---------------- streaming combine: no barriers ----------------
__global__ __launch_bounds__(256)
void combine_kernel(const float* __restrict__ w,
                    const float* __restrict__ g2, const float* __restrict__ be2,
                    float* __restrict__ out)
{
    const int b = blockIdx.x, tid = threadIdx.x;
    float acc[4] = {0.f, 0.f, 0.f, 0.f};
    #pragma unroll
    for (int e = 0; e < NE; e++) {
        const __half* yr = g_Yh + ((size_t)e * NB + b) * NOUT;
        const uint2 u = *(const uint2*)(yr + tid * 4);
        float2 f0 = __half22float2(*(const __half2*)&u.x);
        float2 f1 = __half22float2(*(const __half2*)&u.y);
        const float2 st = g_St[(size_t)e * NB + b];
        const float mean = st.x, rstd = st.y;
        const float we = w[(size_t)b * NE + e];
        const float4 g4 = *(const float4*)(g2 + (size_t)e * NOUT + tid * 4);
        const float4 b4 = *(const float4*)(be2 + (size_t)e * NOUT + tid * 4);
        acc[0] += we * gelu_exact((f0.x - mean) * rstd * g4.x + b4.x);
        acc[1] += we * gelu_exact((f0.y - mean) * rstd * g4.y + b4.y);
        acc[2] += we * gelu_exact((f1.x - mean) * rstd * g4.z + b4.z);
        acc[3] += we * gelu_exact((f1.y - mean) * rstd * g4.w + b4.w);
    }
    *(float4*)(out + (size_t)b * NOUT + tid * 4) =
        make_float4(acc[0], acc[1], acc[2], acc[3]);
}

// ---------------------------------------------------------------------------
extern "C" void kernel_launch(void* const* d_in, const int* in_sizes, int n_in,
                              void* d_out, int out_size)
{
    const float* x   = (const float*)d_in[0];
    const float* wts = (const float*)d_in[1];
    const float* W1  = (const float*)d_in[2];
    const float* b1  = (const float*)d_in[3];
    const float* g1  = (const float*)d_in[4];
    const float* be1 = (const float*)d_in[5];
    const float* W2  = (const float*)d_in[6];
    const float* b2  = (const float*)d_in[7];
    const float* g2  = (const float*)d_in[8];
    const float* be2 = (const float*)d_in[9];
    float* out = (float*)d_out;

    static __half *Xh = nullptr, *Wh1, *Wh2, *Hh, *Yh;
    static float2* St;
    if (!Xh) {
        cudaGetSymbolAddress((void**)&Xh,  g_Xh);
        cudaGetSymbolAddress((void**)&Wh1, g_Wh1);
        cudaGetSymbolAddress((void**)&Wh2, g_Wh2);
        cudaGetSymbolAddress((void**)&Hh,  g_Hh);
        cudaGetSymbolAddress((void**)&Yh,  g_Yh);
        cudaGetSymbolAddress((void**)&St,  g_St);
        cudaFuncSetAttribute((const void*)gemm_f16<false, true>,
                             cudaFuncAttributeMaxDynamicSharedMemorySize, GSMEM);
        cudaFuncSetAttribute((const void*)gemm_f16<true, true>,
                             cudaFuncAttributeMaxDynamicSharedMemorySize, GSMEM);
    }

    cast_x_kernel<<<NB, 256>>>(x, Xh);
    transpose_cast_kernel<<<dim3(NHID/256, NIN/32, NE), 256>>>(W1, Wh1, NIN, NHID);
    transpose_cast_kernel<<<dim3(NOUT/256, NHID/32, NE), 256>>>(W2, Wh2, NHID, NOUT);

    gemm_f16<false, true><<<dim3(NHID/128, NB/128, NE), 128, GSMEM>>>(
        Xh, Wh1, b1, Hh, NB, NHID, NIN);

    ln_gelu_f16<<<NE * NB, 256>>>(Hh, g1, be1);

    gemm_f16<true, true><<<dim3(NOUT/128, NB/128, NE), 128, GSMEM>>>(
        Hh, Wh2, b2, Yh, NB, NOUT, NHID);

    y_stats_kernel<<<NE * NB / 8, 256>>>(Yh, St);
    combine_kernel<<<NB, 256>>>(wts, g2, be2, out);
}